// round 12
// baseline (speedup 1.0000x reference)
#include <cuda_runtime.h>

#define HID 50
#define NPTS 8192
#define NPARA 5000
#define WARPS_PER_BLOCK 8
#define THREADS (WARPS_PER_BLOCK * 32)
#define NBLOCKS 444                      // exactly 3 CTAs per SM on 148 SMs
#define TOTAL_WARPS (NBLOCKS * WARPS_PER_BLOCK)   // 3552
#define NTASKS (NPTS / 2)                // 4096 two-point tasks; 544 extras

// shared layout (floats)
#define OFF_WIN 0
#define OFF_BIN 150
#define OFF_WH  200
#define OFF_BH  10200
#define OFF_WO  10400
#define OFF_BO  10500
#define OFF_STATE 10504                 // 16B aligned
#define STATE_STRIDE 600                // 2 points x (stA 50x4 + stB 50x2)
#define OFF_OUT16 (OFF_STATE + WARPS_PER_BLOCK * STATE_STRIDE)  // 15304
#define OFF_PART (OFF_OUT16 + WARPS_PER_BLOCK * 16)             // 15432
#define SMEM_FLOATS (OFF_PART + WARPS_PER_BLOCK * 12)           // 15528
#define SMEM_BYTES (SMEM_FLOATS * 4)    // ~60.7 KB -> 3 CTAs/SM = 182KB/SM

typedef unsigned long long u64;

__device__ double g_sums[6];            // zero-initialized at load; reset after finalize

__device__ __forceinline__ u64 pack2(float lo, float hi) {
    u64 r; asm("mov.b64 %0, {%1, %2};" : "=l"(r) : "f"(lo), "f"(hi)); return r;
}
__device__ __forceinline__ void unpack2(u64 v, float& lo, float& hi) {
    asm("mov.b64 {%0, %1}, %2;" : "=f"(lo), "=f"(hi) : "l"(v));
}
// d.lo += a.lo*b.lo ; d.hi += a.hi*b.hi   (SASS FFMA2, PTX-only)
__device__ __forceinline__ void ffma2(u64& d, u64 a, u64 b) {
    asm("fma.rn.f32x2 %0, %1, %2, %0;" : "+l"(d) : "l"(a), "l"(b));
}

// tanh(z) and sech^2(z): r = 1/(e^{2z}+1); h = 1-2r; 1-h^2 = 4r(1-r)
__device__ __forceinline__ void tanh_s(float z, float& h, float& s) {
    float e = __expf(2.0f * z);
    float r = __fdividef(1.0f, e + 1.0f);
    h = 1.0f - 2.0f * r;
    s = 4.0f * r * (1.0f - r);
}

// tanh chain + split-array state write for one unit of one point
__device__ __forceinline__ void chain_store(float* stA, float* stB, int j,
                                            float z, float zx, float zxx,
                                            float zy, float zyy, float zt) {
    float h, s; tanh_s(z, h, s);
    float d0  = s * zx;
    float dd0 = fmaf(-2.0f * h * d0, zx, s * zxx);
    float d1  = s * zy;
    float dd1 = fmaf(-2.0f * h * d1, zy, s * zyy);
    float d2  = s * zt;
    ((float4*)stA)[j] = make_float4(h, d0, dd0, d1);
    ((float2*)stB)[j] = make_float2(dd1, d2);
}

__global__ void __launch_bounds__(THREADS) pinn_kernel(
    const float* __restrict__ x,
    const float* __restrict__ W_in, const float* __restrict__ b_in,
    const float* __restrict__ W_hid, const float* __restrict__ b_hid,
    const float* __restrict__ W_out, const float* __restrict__ b_out)
{
    extern __shared__ float sm[];
    const int tid = threadIdx.x;

    for (int i = tid; i < 2500; i += THREADS)
        ((float4*)(sm + OFF_WH))[i] = ((const float4*)W_hid)[i];
    for (int i = tid; i < 150;  i += THREADS) sm[OFF_WIN + i] = W_in[i];
    for (int i = tid; i < 50;   i += THREADS) sm[OFF_BIN + i] = b_in[i];
    for (int i = tid; i < 200;  i += THREADS) sm[OFF_BH  + i] = b_hid[i];
    for (int i = tid; i < 100;  i += THREADS) sm[OFF_WO  + i] = W_out[i];
    if (tid < 2) sm[OFF_BO + tid] = b_out[tid];
    for (int i = tid; i < WARPS_PER_BLOCK * 12; i += THREADS)
        sm[OFF_PART + i] = 0.0f;        // per-warp residual accumulators
    __syncthreads();

    const int warp = tid >> 5;
    const int lane = tid & 31;
    const int gwarp = blockIdx.x * WARPS_PER_BLOCK + warp;
    float* stA0 = sm + OFF_STATE + warp * STATE_STRIDE;     // pt0: 50x{h,dx,dxx,dy}
    float* stB0 = stA0 + 200;                               //      50x{dyy,dt}
    float* stA1 = stA0 + 300;                               // pt1
    float* stB1 = stA1 + 200;

    const int j1 = lane;
    const int j2 = lane + 32;
    const bool has2 = (j2 < HID);

    // ---- Bresenham-spread extras: 544/3552 = 17/111. Warp w doubled iff
    // (17w mod 111) >= 94; its extra task = 3552 + floor(17w/111), each of
    // 3552..4095 assigned exactly once, doubled warps recur every ~6.5 warps
    // (scattered across CTAs and warp slots -> across SMs and SMSPs).
    const int w17 = gwarp * 17;
    const int extra = ((w17 % 111) >= 94) ? (TOTAL_WARPS + w17 / 111) : -1;

    for (int rep = 0; rep < 2; rep++) {
        const int task = rep ? extra : gwarp;
        if (task < 0) break;
        const int p0 = task * 2;
        const float x00 = x[p0 * 3 + 0], x01 = x[p0 * 3 + 1], x02 = x[p0 * 3 + 2];
        const float x10 = x[p0 * 3 + 3], x11 = x[p0 * 3 + 4], x12 = x[p0 * 3 + 5];
        __syncwarp();   // prior task's epilogue reads done before overwrite

        // ---- input layer for both points
        #pragma unroll
        for (int o = 0; o < 2; o++) {
            int j = lane + 32 * o;
            if (j < HID) {
                float w0 = sm[OFF_WIN + j];
                float w1 = sm[OFF_WIN + 50 + j];
                float w2 = sm[OFF_WIN + 100 + j];
                float bj = sm[OFF_BIN + j];
                {
                    float z = bj + x00 * w0 + x01 * w1 + x02 * w2;
                    float h, s; tanh_s(z, h, s);
                    float d0 = s * w0, dd0 = -2.0f * h * d0 * w0;
                    float d1 = s * w1, dd1 = -2.0f * h * d1 * w1;
                    float d2 = s * w2;
                    ((float4*)stA0)[j] = make_float4(h, d0, dd0, d1);
                    ((float2*)stB0)[j] = make_float2(dd1, d2);
                }
                {
                    float z = bj + x10 * w0 + x11 * w1 + x12 * w2;
                    float h, s; tanh_s(z, h, s);
                    float d0 = s * w0, dd0 = -2.0f * h * d0 * w0;
                    float d1 = s * w1, dd1 = -2.0f * h * d1 * w1;
                    float d2 = s * w2;
                    ((float4*)stA1)[j] = make_float4(h, d0, dd0, d1);
                    ((float2*)stB1)[j] = make_float2(dd1, d2);
                }
            }
        }
        __syncwarp();

        // ---- 4 hidden layers: identical loads to R8, arithmetic as 12 FFMA2/k
        for (int l = 0; l < 4; l++) {
            const float* Wl = sm + OFF_WH + l * 2500;
            const float* bl = sm + OFF_BH + l * 50;
            float b1 = bl[j1], b2 = has2 ? bl[j2] : 0.0f;

            // pair layout: {z,zx} {zxx,zy} {zyy,zt}
            u64 P0a = pack2(b1, 0.0f), P1a = 0ull, P2a = 0ull;
            u64 P0b = pack2(b2, 0.0f), P1b = 0ull, P2b = 0ull;
            u64 Q0a = pack2(b1, 0.0f), Q1a = 0ull, Q2a = 0ull;
            u64 Q0b = pack2(b2, 0.0f), Q1b = 0ull, Q2b = 0ull;

            #pragma unroll
            for (int k = 0; k < HID; k++) {
                float w1 = Wl[k * 50 + j1];                  // LDS.32, 1 wf
                float w2 = has2 ? Wl[k * 50 + j2] : 0.0f;    // LDS.32, 1 wf
                u64 ww1 = pack2(w1, w1);
                u64 ww2 = pack2(w2, w2);
                ulonglong2 A0 = ((const ulonglong2*)stA0)[k]; // LDS.128 bcast
                u64        B0 = ((const u64*)stB0)[k];        // LDS.64  bcast
                ulonglong2 A1 = ((const ulonglong2*)stA1)[k];
                u64        B1 = ((const u64*)stB1)[k];
                ffma2(P0a, A0.x, ww1); ffma2(P1a, A0.y, ww1); ffma2(P2a, B0, ww1);
                ffma2(P0b, A0.x, ww2); ffma2(P1b, A0.y, ww2); ffma2(P2b, B0, ww2);
                ffma2(Q0a, A1.x, ww1); ffma2(Q1a, A1.y, ww1); ffma2(Q2a, B1, ww1);
                ffma2(Q0b, A1.x, ww2); ffma2(Q1b, A1.y, ww2); ffma2(Q2b, B1, ww2);
            }
            __syncwarp();   // all reads of old state complete before overwrite
            {
                float z, zx, zxx, zy, zyy, zt;
                unpack2(P0a, z, zx); unpack2(P1a, zxx, zy); unpack2(P2a, zyy, zt);
                chain_store(stA0, stB0, j1, z, zx, zxx, zy, zyy, zt);
                unpack2(Q0a, z, zx); unpack2(Q1a, zxx, zy); unpack2(Q2a, zyy, zt);
                chain_store(stA1, stB1, j1, z, zx, zxx, zy, zyy, zt);
            }
            if (has2) {
                float z, zx, zxx, zy, zyy, zt;
                unpack2(P0b, z, zx); unpack2(P1b, zxx, zy); unpack2(P2b, zyy, zt);
                chain_store(stA0, stB0, j2, z, zx, zxx, zy, zyy, zt);
                unpack2(Q0b, z, zx); unpack2(Q1b, zxx, zy); unpack2(Q2b, zyy, zt);
                chain_store(stA1, stB1, j2, z, zx, zxx, zy, zyy, zt);
            }
            __syncwarp();
        }

        // ---- output layer: 8 dot products per point; lanes 0-7 pt0, 8-15 pt1
        if (lane < 16) {
            int pt = lane >> 3;
            int l8 = lane & 7;
            int cidx = l8 >> 1;              // 0=val, 1=dxx, 2=dyy, 3=dt
            int o = l8 & 1;
            float* sA = pt ? stA1 : stA0;
            float* sB = pt ? stB1 : stB0;
            const float* cp = (cidx < 2) ? (sA + 2 * cidx) : (sB + (cidx - 2));
            int cstr = (cidx < 2) ? 4 : 2;
            float acc0 = (cidx == 0) ? sm[OFF_BO + o] : 0.0f;
            float acc1 = 0.0f;
            #pragma unroll
            for (int k = 0; k < HID; k += 2) {
                acc0 = fmaf(cp[k * cstr],       sm[OFF_WO + k * 2 + o],       acc0);
                acc1 = fmaf(cp[(k + 1) * cstr], sm[OFF_WO + (k + 1) * 2 + o], acc1);
            }
            sm[OFF_OUT16 + warp * 16 + lane] = acc0 + acc1;
        }
        __syncwarp();

        if (lane < 2) {                      // lane 0 -> pt0, lane 1 -> pt1
            const float* o8 = sm + OFF_OUT16 + warp * 16 + lane * 8;
            float u   = o8[0], v   = o8[1];
            float uxx = o8[2], vxx = o8[3];
            float uyy = o8[4], vyy = o8[5];
            float ut  = o8[6], vt  = o8[7];
            float Q  = u * u + v * v;
            float A1 = vt - 0.5f * uxx - 0.5f * vyy - Q * u + v;
            float A2 = ut + 0.5f * vxx - 0.5f * uyy + Q * v + u;
            float B1 = uyy, B2 = vyy;
            float C1 = Q * v, C2 = Q * u;
            float* pp = sm + OFF_PART + (warp * 2 + lane) * 6;
            pp[0] += A1 * A1 + A2 * A2;
            pp[1] += B1 * B1 + B2 * B2;
            pp[2] += C1 * C1 + C2 * C2;
            pp[3] += A2 * B2 - A1 * B1;
            pp[4] += A1 * C1 + A2 * C2;
            pp[5] += B1 * C1 - B2 * C2;
        }
    }
    __syncthreads();

    if (tid < 6) {
        double s = 0.0;
        #pragma unroll
        for (int w = 0; w < WARPS_PER_BLOCK * 2; w++)
            s += (double)sm[OFF_PART + w * 6 + tid];
        atomicAdd(&g_sums[tid], s);
    }
}

__global__ void finalize_kernel(const float* __restrict__ para, float* __restrict__ out) {
    int p = blockIdx.x * blockDim.x + threadIdx.x;
    if (p < NPARA) {
        double a = (double)para[p * 3 + 0];
        double c = (double)para[p * 3 + 2];
        double r = g_sums[0]
                 + 0.25 * a * a * g_sums[1]
                 + c * c * g_sums[2]
                 + a * g_sums[3]
                 - 2.0 * c * g_sums[4]
                 + a * c * g_sums[5];
        out[p] = (float)(r * (1.0 / (double)NPTS));
    }
}

__global__ void reset_kernel() {
    if (threadIdx.x < 6) g_sums[threadIdx.x] = 0.0;
}

extern "C" void kernel_launch(void* const* d_in, const int* in_sizes, int n_in,
                              void* d_out, int out_size) {
    const float* x     = (const float*)d_in[0];
    const float* para  = (const float*)d_in[1];
    const float* W_in  = (const float*)d_in[2];
    const float* b_in  = (const float*)d_in[3];
    const float* W_hid = (const float*)d_in[4];
    const float* b_hid = (const float*)d_in[5];
    const float* W_out = (const float*)d_in[6];
    const float* b_out = (const float*)d_in[7];
    float* out = (float*)d_out;

    cudaFuncSetAttribute(pinn_kernel, cudaFuncAttributeMaxDynamicSharedMemorySize, SMEM_BYTES);
    pinn_kernel<<<NBLOCKS, THREADS, SMEM_BYTES>>>(
        x, W_in, b_in, W_hid, b_hid, W_out, b_out);
    finalize_kernel<<<(NPARA + 255) / 256, 256>>>(para, out);
    reset_kernel<<<1, 32>>>();
}

// round 13
// speedup vs baseline: 1.0384x; 1.0384x over previous
#include <cuda_runtime.h>

#define HID 50
#define NPTS 8192
#define NPARA 5000
#define WARPS_PER_BLOCK 8
#define THREADS (WARPS_PER_BLOCK * 32)
#define NBLOCKS 296                      // exactly 2 CTAs per SM on 148 SMs
#define TOTAL_WARPS (NBLOCKS * WARPS_PER_BLOCK)   // 2368
#define NTASKS (NPTS / 2)                // 4096 two-point tasks

// shared layout (floats)
#define OFF_WIN 0
#define OFF_BIN 150
#define OFF_WH  200
#define OFF_BH  10200
#define OFF_WO  10400
#define OFF_BO  10500
#define OFF_STATE 10504                 // 16B aligned
#define STATE_STRIDE 600                // 2 points x (stA 50x4 + stB 50x2)
#define OFF_OUT16 (OFF_STATE + WARPS_PER_BLOCK * STATE_STRIDE)  // 15304
#define OFF_PART (OFF_OUT16 + WARPS_PER_BLOCK * 16)             // 15432
#define SMEM_FLOATS (OFF_PART + WARPS_PER_BLOCK * 12)           // 15528
#define SMEM_BYTES (SMEM_FLOATS * 4)    // ~60.7 KB

typedef unsigned long long u64;

__device__ double g_sums[6];            // zero-initialized at load; reset after finalize

__device__ __forceinline__ u64 pack2(float lo, float hi) {
    u64 r; asm("mov.b64 %0, {%1, %2};" : "=l"(r) : "f"(lo), "f"(hi)); return r;
}
__device__ __forceinline__ void unpack2(u64 v, float& lo, float& hi) {
    asm("mov.b64 {%0, %1}, %2;" : "=f"(lo), "=f"(hi) : "l"(v));
}
// d.lo += a.lo*b.lo ; d.hi += a.hi*b.hi   (SASS FFMA2, PTX-only)
__device__ __forceinline__ void ffma2(u64& d, u64 a, u64 b) {
    asm("fma.rn.f32x2 %0, %1, %2, %0;" : "+l"(d) : "l"(a), "l"(b));
}

// tanh(z) and sech^2(z): r = 1/(e^{2z}+1); h = 1-2r; 1-h^2 = 4r(1-r)
__device__ __forceinline__ void tanh_s(float z, float& h, float& s) {
    float e = __expf(2.0f * z);
    float r = __fdividef(1.0f, e + 1.0f);
    h = 1.0f - 2.0f * r;
    s = 4.0f * r * (1.0f - r);
}

// tanh chain + split-array state write for one unit of one point
__device__ __forceinline__ void chain_store(float* stA, float* stB, int j,
                                            float z, float zx, float zxx,
                                            float zy, float zyy, float zt) {
    float h, s; tanh_s(z, h, s);
    float d0  = s * zx;
    float dd0 = fmaf(-2.0f * h * d0, zx, s * zxx);
    float d1  = s * zy;
    float dd1 = fmaf(-2.0f * h * d1, zy, s * zyy);
    float d2  = s * zt;
    ((float4*)stA)[j] = make_float4(h, d0, dd0, d1);
    ((float2*)stB)[j] = make_float2(dd1, d2);
}

__global__ void __launch_bounds__(THREADS, 2) pinn_kernel(
    const float* __restrict__ x,
    const float* __restrict__ W_in, const float* __restrict__ b_in,
    const float* __restrict__ W_hid, const float* __restrict__ b_hid,
    const float* __restrict__ W_out, const float* __restrict__ b_out)
{
    extern __shared__ float sm[];
    const int tid = threadIdx.x;

    for (int i = tid; i < 2500; i += THREADS)
        ((float4*)(sm + OFF_WH))[i] = ((const float4*)W_hid)[i];
    for (int i = tid; i < 150;  i += THREADS) sm[OFF_WIN + i] = W_in[i];
    for (int i = tid; i < 50;   i += THREADS) sm[OFF_BIN + i] = b_in[i];
    for (int i = tid; i < 200;  i += THREADS) sm[OFF_BH  + i] = b_hid[i];
    for (int i = tid; i < 100;  i += THREADS) sm[OFF_WO  + i] = W_out[i];
    if (tid < 2) sm[OFF_BO + tid] = b_out[tid];
    for (int i = tid; i < WARPS_PER_BLOCK * 12; i += THREADS)
        sm[OFF_PART + i] = 0.0f;        // per-warp residual accumulators
    __syncthreads();

    const int warp = tid >> 5;
    const int lane = tid & 31;
    const int gwarp = blockIdx.x * WARPS_PER_BLOCK + warp;
    float* stA0 = sm + OFF_STATE + warp * STATE_STRIDE;     // pt0: 50x{h,dx,dxx,dy}
    float* stB0 = stA0 + 200;                               //      50x{dyy,dt}
    float* stA1 = stA0 + 300;                               // pt1
    float* stB1 = stA1 + 200;

    const int j1 = lane;
    const int j2 = lane + 32;
    const bool has2 = (j2 < HID);

    for (int task = gwarp; task < NTASKS; task += TOTAL_WARPS) {
        const int p0 = task * 2;
        const float x00 = x[p0 * 3 + 0], x01 = x[p0 * 3 + 1], x02 = x[p0 * 3 + 2];
        const float x10 = x[p0 * 3 + 3], x11 = x[p0 * 3 + 4], x12 = x[p0 * 3 + 5];
        __syncwarp();   // prior task's epilogue reads done before overwrite

        // ---- input layer for both points
        #pragma unroll
        for (int o = 0; o < 2; o++) {
            int j = lane + 32 * o;
            if (j < HID) {
                float w0 = sm[OFF_WIN + j];
                float w1 = sm[OFF_WIN + 50 + j];
                float w2 = sm[OFF_WIN + 100 + j];
                float bj = sm[OFF_BIN + j];
                {
                    float z = bj + x00 * w0 + x01 * w1 + x02 * w2;
                    float h, s; tanh_s(z, h, s);
                    float d0 = s * w0, dd0 = -2.0f * h * d0 * w0;
                    float d1 = s * w1, dd1 = -2.0f * h * d1 * w1;
                    float d2 = s * w2;
                    ((float4*)stA0)[j] = make_float4(h, d0, dd0, d1);
                    ((float2*)stB0)[j] = make_float2(dd1, d2);
                }
                {
                    float z = bj + x10 * w0 + x11 * w1 + x12 * w2;
                    float h, s; tanh_s(z, h, s);
                    float d0 = s * w0, dd0 = -2.0f * h * d0 * w0;
                    float d1 = s * w1, dd1 = -2.0f * h * d1 * w1;
                    float d2 = s * w2;
                    ((float4*)stA1)[j] = make_float4(h, d0, dd0, d1);
                    ((float2*)stB1)[j] = make_float2(dd1, d2);
                }
            }
        }
        __syncwarp();

        // ---- 4 hidden layers: identical loads to R8, arithmetic as 12 FFMA2/k
        for (int l = 0; l < 4; l++) {
            const float* Wl = sm + OFF_WH + l * 2500;
            const float* bl = sm + OFF_BH + l * 50;
            float b1 = bl[j1], b2 = has2 ? bl[j2] : 0.0f;

            // pair layout: {z,zx} {zxx,zy} {zyy,zt}
            u64 P0a = pack2(b1, 0.0f), P1a = 0ull, P2a = 0ull;
            u64 P0b = pack2(b2, 0.0f), P1b = 0ull, P2b = 0ull;
            u64 Q0a = pack2(b1, 0.0f), Q1a = 0ull, Q2a = 0ull;
            u64 Q0b = pack2(b2, 0.0f), Q1b = 0ull, Q2b = 0ull;

            #pragma unroll
            for (int k = 0; k < HID; k++) {
                float w1 = Wl[k * 50 + j1];                  // LDS.32, 1 wf
                float w2 = has2 ? Wl[k * 50 + j2] : 0.0f;    // LDS.32, 1 wf
                u64 ww1 = pack2(w1, w1);
                u64 ww2 = pack2(w2, w2);
                ulonglong2 A0 = ((const ulonglong2*)stA0)[k]; // LDS.128 bcast
                u64        B0 = ((const u64*)stB0)[k];        // LDS.64  bcast
                ulonglong2 A1 = ((const ulonglong2*)stA1)[k];
                u64        B1 = ((const u64*)stB1)[k];
                ffma2(P0a, A0.x, ww1); ffma2(P1a, A0.y, ww1); ffma2(P2a, B0, ww1);
                ffma2(P0b, A0.x, ww2); ffma2(P1b, A0.y, ww2); ffma2(P2b, B0, ww2);
                ffma2(Q0a, A1.x, ww1); ffma2(Q1a, A1.y, ww1); ffma2(Q2a, B1, ww1);
                ffma2(Q0b, A1.x, ww2); ffma2(Q1b, A1.y, ww2); ffma2(Q2b, B1, ww2);
            }
            __syncwarp();   // all reads of old state complete before overwrite
            {
                float z, zx, zxx, zy, zyy, zt;
                unpack2(P0a, z, zx); unpack2(P1a, zxx, zy); unpack2(P2a, zyy, zt);
                chain_store(stA0, stB0, j1, z, zx, zxx, zy, zyy, zt);
                unpack2(Q0a, z, zx); unpack2(Q1a, zxx, zy); unpack2(Q2a, zyy, zt);
                chain_store(stA1, stB1, j1, z, zx, zxx, zy, zyy, zt);
            }
            if (has2) {
                float z, zx, zxx, zy, zyy, zt;
                unpack2(P0b, z, zx); unpack2(P1b, zxx, zy); unpack2(P2b, zyy, zt);
                chain_store(stA0, stB0, j2, z, zx, zxx, zy, zyy, zt);
                unpack2(Q0b, z, zx); unpack2(Q1b, zxx, zy); unpack2(Q2b, zyy, zt);
                chain_store(stA1, stB1, j2, z, zx, zxx, zy, zyy, zt);
            }
            __syncwarp();
        }

        // ---- output layer: 8 dot products per point; lanes 0-7 pt0, 8-15 pt1
        if (lane < 16) {
            int pt = lane >> 3;
            int l8 = lane & 7;
            int cidx = l8 >> 1;              // 0=val, 1=dxx, 2=dyy, 3=dt
            int o = l8 & 1;
            float* sA = pt ? stA1 : stA0;
            float* sB = pt ? stB1 : stB0;
            const float* cp = (cidx < 2) ? (sA + 2 * cidx) : (sB + (cidx - 2));
            int cstr = (cidx < 2) ? 4 : 2;
            float acc0 = (cidx == 0) ? sm[OFF_BO + o] : 0.0f;
            float acc1 = 0.0f;
            #pragma unroll
            for (int k = 0; k < HID; k += 2) {
                acc0 = fmaf(cp[k * cstr],       sm[OFF_WO + k * 2 + o],       acc0);
                acc1 = fmaf(cp[(k + 1) * cstr], sm[OFF_WO + (k + 1) * 2 + o], acc1);
            }
            sm[OFF_OUT16 + warp * 16 + lane] = acc0 + acc1;
        }
        __syncwarp();

        if (lane < 2) {                      // lane 0 -> pt0, lane 1 -> pt1
            const float* o8 = sm + OFF_OUT16 + warp * 16 + lane * 8;
            float u   = o8[0], v   = o8[1];
            float uxx = o8[2], vxx = o8[3];
            float uyy = o8[4], vyy = o8[5];
            float ut  = o8[6], vt  = o8[7];
            float Q  = u * u + v * v;
            float A1 = vt - 0.5f * uxx - 0.5f * vyy - Q * u + v;
            float A2 = ut + 0.5f * vxx - 0.5f * uyy + Q * v + u;
            float B1 = uyy, B2 = vyy;
            float C1 = Q * v, C2 = Q * u;
            float* pp = sm + OFF_PART + (warp * 2 + lane) * 6;
            pp[0] += A1 * A1 + A2 * A2;
            pp[1] += B1 * B1 + B2 * B2;
            pp[2] += C1 * C1 + C2 * C2;
            pp[3] += A2 * B2 - A1 * B1;
            pp[4] += A1 * C1 + A2 * C2;
            pp[5] += B1 * C1 - B2 * C2;
        }
    }
    __syncthreads();

    if (tid < 6) {
        double s = 0.0;
        #pragma unroll
        for (int w = 0; w < WARPS_PER_BLOCK * 2; w++)
            s += (double)sm[OFF_PART + w * 6 + tid];
        atomicAdd(&g_sums[tid], s);
    }
}

__global__ void finalize_kernel(const float* __restrict__ para, float* __restrict__ out) {
    int p = blockIdx.x * blockDim.x + threadIdx.x;
    if (p < NPARA) {
        double a = (double)para[p * 3 + 0];
        double c = (double)para[p * 3 + 2];
        double r = g_sums[0]
                 + 0.25 * a * a * g_sums[1]
                 + c * c * g_sums[2]
                 + a * g_sums[3]
                 - 2.0 * c * g_sums[4]
                 + a * c * g_sums[5];
        out[p] = (float)(r * (1.0 / (double)NPTS));
    }
}

__global__ void reset_kernel() {
    if (threadIdx.x < 6) g_sums[threadIdx.x] = 0.0;
}

extern "C" void kernel_launch(void* const* d_in, const int* in_sizes, int n_in,
                              void* d_out, int out_size) {
    const float* x     = (const float*)d_in[0];
    const float* para  = (const float*)d_in[1];
    const float* W_in  = (const float*)d_in[2];
    const float* b_in  = (const float*)d_in[3];
    const float* W_hid = (const float*)d_in[4];
    const float* b_hid = (const float*)d_in[5];
    const float* W_out = (const float*)d_in[6];
    const float* b_out = (const float*)d_in[7];
    float* out = (float*)d_out;

    cudaFuncSetAttribute(pinn_kernel, cudaFuncAttributeMaxDynamicSharedMemorySize, SMEM_BYTES);
    pinn_kernel<<<NBLOCKS, THREADS, SMEM_BYTES>>>(
        x, W_in, b_in, W_hid, b_hid, W_out, b_out);
    finalize_kernel<<<(NPARA + 255) / 256, 256>>>(para, out);
    reset_kernel<<<1, 32>>>();
}

// round 14
// speedup vs baseline: 1.0442x; 1.0056x over previous
#include <cuda_runtime.h>

#define HID 50
#define NPTS 8192
#define NPARA 5000
#define WARPS_PER_BLOCK 8
#define THREADS (WARPS_PER_BLOCK * 32)
#define NBLOCKS 296                      // exactly 2 CTAs per SM on 148 SMs
#define TOTAL_WARPS (NBLOCKS * WARPS_PER_BLOCK)   // 2368
#define NTASKS (NPTS / 2)                // 4096 two-point tasks

// shared layout (floats)
#define OFF_WIN 0
#define OFF_BIN 150
#define OFF_WH  200
#define OFF_BH  10200
#define OFF_WO  10400
#define OFF_BO  10500
#define OFF_STATE 10504                 // 16B aligned
#define STATE_STRIDE 600                // 2 points x (stA 50x4 + stB 50x2)
#define OFF_OUT16 (OFF_STATE + WARPS_PER_BLOCK * STATE_STRIDE)  // 15304
#define OFF_PART (OFF_OUT16 + WARPS_PER_BLOCK * 16)             // 15432
#define SMEM_FLOATS (OFF_PART + WARPS_PER_BLOCK * 12)           // 15528
#define SMEM_BYTES (SMEM_FLOATS * 4)    // ~60.7 KB

typedef unsigned long long u64;

__device__ double g_sums[6];            // zero-initialized at load; reset after finalize
__device__ unsigned int g_next;         // dynamic task counter; reset after finalize

__device__ __forceinline__ u64 pack2(float lo, float hi) {
    u64 r; asm("mov.b64 %0, {%1, %2};" : "=l"(r) : "f"(lo), "f"(hi)); return r;
}
__device__ __forceinline__ void unpack2(u64 v, float& lo, float& hi) {
    asm("mov.b64 {%0, %1}, %2;" : "=f"(lo), "=f"(hi) : "l"(v));
}
// d.lo += a.lo*b.lo ; d.hi += a.hi*b.hi   (SASS FFMA2, PTX-only)
__device__ __forceinline__ void ffma2(u64& d, u64 a, u64 b) {
    asm("fma.rn.f32x2 %0, %1, %2, %0;" : "+l"(d) : "l"(a), "l"(b));
}

// tanh(z) and sech^2(z): r = 1/(e^{2z}+1); h = 1-2r; 1-h^2 = 4r(1-r)
__device__ __forceinline__ void tanh_s(float z, float& h, float& s) {
    float e = __expf(2.0f * z);
    float r = __fdividef(1.0f, e + 1.0f);
    h = 1.0f - 2.0f * r;
    s = 4.0f * r * (1.0f - r);
}

// tanh chain + split-array state write for one unit of one point
__device__ __forceinline__ void chain_store(float* stA, float* stB, int j,
                                            float z, float zx, float zxx,
                                            float zy, float zyy, float zt) {
    float h, s; tanh_s(z, h, s);
    float d0  = s * zx;
    float dd0 = fmaf(-2.0f * h * d0, zx, s * zxx);
    float d1  = s * zy;
    float dd1 = fmaf(-2.0f * h * d1, zy, s * zyy);
    float d2  = s * zt;
    ((float4*)stA)[j] = make_float4(h, d0, dd0, d1);
    ((float2*)stB)[j] = make_float2(dd1, d2);
}

__global__ void __launch_bounds__(THREADS, 2) pinn_kernel(
    const float* __restrict__ x,
    const float* __restrict__ W_in, const float* __restrict__ b_in,
    const float* __restrict__ W_hid, const float* __restrict__ b_hid,
    const float* __restrict__ W_out, const float* __restrict__ b_out)
{
    extern __shared__ float sm[];
    const int tid = threadIdx.x;

    for (int i = tid; i < 2500; i += THREADS)
        ((float4*)(sm + OFF_WH))[i] = ((const float4*)W_hid)[i];
    for (int i = tid; i < 150;  i += THREADS) sm[OFF_WIN + i] = W_in[i];
    for (int i = tid; i < 50;   i += THREADS) sm[OFF_BIN + i] = b_in[i];
    for (int i = tid; i < 200;  i += THREADS) sm[OFF_BH  + i] = b_hid[i];
    for (int i = tid; i < 100;  i += THREADS) sm[OFF_WO  + i] = W_out[i];
    if (tid < 2) sm[OFF_BO + tid] = b_out[tid];
    for (int i = tid; i < WARPS_PER_BLOCK * 12; i += THREADS)
        sm[OFF_PART + i] = 0.0f;        // per-warp residual accumulators
    __syncthreads();

    const int warp = tid >> 5;
    const int lane = tid & 31;
    const int gwarp = blockIdx.x * WARPS_PER_BLOCK + warp;
    float* stA0 = sm + OFF_STATE + warp * STATE_STRIDE;     // pt0: 50x{h,dx,dxx,dy}
    float* stB0 = stA0 + 200;                               //      50x{dyy,dt}
    float* stA1 = stA0 + 300;                               // pt1
    float* stB1 = stA1 + 200;

    const int j1 = lane;
    const int j2 = lane + 32;
    const bool has2 = (j2 < HID);

    // ---- work-stealing: first TOTAL_WARPS tasks static, rest via atomic queue.
    int task = gwarp;
    while (task < NTASKS) {
        // prefetch NEXT task id now; ~318cyc ATOMG latency hides under compute
        unsigned nt = 0;
        if (lane == 0) nt = atomicAdd(&g_next, 1u);
        nt = __shfl_sync(0xffffffffu, nt, 0);
        const int next_task = TOTAL_WARPS + (int)nt;

        const int p0 = task * 2;
        const float x00 = x[p0 * 3 + 0], x01 = x[p0 * 3 + 1], x02 = x[p0 * 3 + 2];
        const float x10 = x[p0 * 3 + 3], x11 = x[p0 * 3 + 4], x12 = x[p0 * 3 + 5];
        __syncwarp();   // prior task's epilogue reads done before overwrite

        // ---- input layer for both points
        #pragma unroll
        for (int o = 0; o < 2; o++) {
            int j = lane + 32 * o;
            if (j < HID) {
                float w0 = sm[OFF_WIN + j];
                float w1 = sm[OFF_WIN + 50 + j];
                float w2 = sm[OFF_WIN + 100 + j];
                float bj = sm[OFF_BIN + j];
                {
                    float z = bj + x00 * w0 + x01 * w1 + x02 * w2;
                    float h, s; tanh_s(z, h, s);
                    float d0 = s * w0, dd0 = -2.0f * h * d0 * w0;
                    float d1 = s * w1, dd1 = -2.0f * h * d1 * w1;
                    float d2 = s * w2;
                    ((float4*)stA0)[j] = make_float4(h, d0, dd0, d1);
                    ((float2*)stB0)[j] = make_float2(dd1, d2);
                }
                {
                    float z = bj + x10 * w0 + x11 * w1 + x12 * w2;
                    float h, s; tanh_s(z, h, s);
                    float d0 = s * w0, dd0 = -2.0f * h * d0 * w0;
                    float d1 = s * w1, dd1 = -2.0f * h * d1 * w1;
                    float d2 = s * w2;
                    ((float4*)stA1)[j] = make_float4(h, d0, dd0, d1);
                    ((float2*)stB1)[j] = make_float2(dd1, d2);
                }
            }
        }
        __syncwarp();

        // ---- 4 hidden layers: identical loads to R8, arithmetic as 12 FFMA2/k
        for (int l = 0; l < 4; l++) {
            const float* Wl = sm + OFF_WH + l * 2500;
            const float* bl = sm + OFF_BH + l * 50;
            float b1 = bl[j1], b2 = has2 ? bl[j2] : 0.0f;

            // pair layout: {z,zx} {zxx,zy} {zyy,zt}
            u64 P0a = pack2(b1, 0.0f), P1a = 0ull, P2a = 0ull;
            u64 P0b = pack2(b2, 0.0f), P1b = 0ull, P2b = 0ull;
            u64 Q0a = pack2(b1, 0.0f), Q1a = 0ull, Q2a = 0ull;
            u64 Q0b = pack2(b2, 0.0f), Q1b = 0ull, Q2b = 0ull;

            #pragma unroll
            for (int k = 0; k < HID; k++) {
                float w1 = Wl[k * 50 + j1];                  // LDS.32, 1 wf
                float w2 = has2 ? Wl[k * 50 + j2] : 0.0f;    // LDS.32, 1 wf
                u64 ww1 = pack2(w1, w1);
                u64 ww2 = pack2(w2, w2);
                ulonglong2 A0 = ((const ulonglong2*)stA0)[k]; // LDS.128 bcast
                u64        B0 = ((const u64*)stB0)[k];        // LDS.64  bcast
                ulonglong2 A1 = ((const ulonglong2*)stA1)[k];
                u64        B1 = ((const u64*)stB1)[k];
                ffma2(P0a, A0.x, ww1); ffma2(P1a, A0.y, ww1); ffma2(P2a, B0, ww1);
                ffma2(P0b, A0.x, ww2); ffma2(P1b, A0.y, ww2); ffma2(P2b, B0, ww2);
                ffma2(Q0a, A1.x, ww1); ffma2(Q1a, A1.y, ww1); ffma2(Q2a, B1, ww1);
                ffma2(Q0b, A1.x, ww2); ffma2(Q1b, A1.y, ww2); ffma2(Q2b, B1, ww2);
            }
            __syncwarp();   // all reads of old state complete before overwrite
            {
                float z, zx, zxx, zy, zyy, zt;
                unpack2(P0a, z, zx); unpack2(P1a, zxx, zy); unpack2(P2a, zyy, zt);
                chain_store(stA0, stB0, j1, z, zx, zxx, zy, zyy, zt);
                unpack2(Q0a, z, zx); unpack2(Q1a, zxx, zy); unpack2(Q2a, zyy, zt);
                chain_store(stA1, stB1, j1, z, zx, zxx, zy, zyy, zt);
            }
            if (has2) {
                float z, zx, zxx, zy, zyy, zt;
                unpack2(P0b, z, zx); unpack2(P1b, zxx, zy); unpack2(P2b, zyy, zt);
                chain_store(stA0, stB0, j2, z, zx, zxx, zy, zyy, zt);
                unpack2(Q0b, z, zx); unpack2(Q1b, zxx, zy); unpack2(Q2b, zyy, zt);
                chain_store(stA1, stB1, j2, z, zx, zxx, zy, zyy, zt);
            }
            __syncwarp();
        }

        // ---- output layer: 8 dot products per point; lanes 0-7 pt0, 8-15 pt1
        if (lane < 16) {
            int pt = lane >> 3;
            int l8 = lane & 7;
            int cidx = l8 >> 1;              // 0=val, 1=dxx, 2=dyy, 3=dt
            int o = l8 & 1;
            float* sA = pt ? stA1 : stA0;
            float* sB = pt ? stB1 : stB0;
            const float* cp = (cidx < 2) ? (sA + 2 * cidx) : (sB + (cidx - 2));
            int cstr = (cidx < 2) ? 4 : 2;
            float acc0 = (cidx == 0) ? sm[OFF_BO + o] : 0.0f;
            float acc1 = 0.0f;
            #pragma unroll
            for (int k = 0; k < HID; k += 2) {
                acc0 = fmaf(cp[k * cstr],       sm[OFF_WO + k * 2 + o],       acc0);
                acc1 = fmaf(cp[(k + 1) * cstr], sm[OFF_WO + (k + 1) * 2 + o], acc1);
            }
            sm[OFF_OUT16 + warp * 16 + lane] = acc0 + acc1;
        }
        __syncwarp();

        if (lane < 2) {                      // lane 0 -> pt0, lane 1 -> pt1
            const float* o8 = sm + OFF_OUT16 + warp * 16 + lane * 8;
            float u   = o8[0], v   = o8[1];
            float uxx = o8[2], vxx = o8[3];
            float uyy = o8[4], vyy = o8[5];
            float ut  = o8[6], vt  = o8[7];
            float Q  = u * u + v * v;
            float A1 = vt - 0.5f * uxx - 0.5f * vyy - Q * u + v;
            float A2 = ut + 0.5f * vxx - 0.5f * uyy + Q * v + u;
            float B1 = uyy, B2 = vyy;
            float C1 = Q * v, C2 = Q * u;
            float* pp = sm + OFF_PART + (warp * 2 + lane) * 6;
            pp[0] += A1 * A1 + A2 * A2;
            pp[1] += B1 * B1 + B2 * B2;
            pp[2] += C1 * C1 + C2 * C2;
            pp[3] += A2 * B2 - A1 * B1;
            pp[4] += A1 * C1 + A2 * C2;
            pp[5] += B1 * C1 - B2 * C2;
        }

        task = next_task;
    }
    __syncthreads();

    if (tid < 6) {
        double s = 0.0;
        #pragma unroll
        for (int w = 0; w < WARPS_PER_BLOCK * 2; w++)
            s += (double)sm[OFF_PART + w * 6 + tid];
        atomicAdd(&g_sums[tid], s);
    }
}

__global__ void finalize_kernel(const float* __restrict__ para, float* __restrict__ out) {
    int p = blockIdx.x * blockDim.x + threadIdx.x;
    if (p < NPARA) {
        double a = (double)para[p * 3 + 0];
        double c = (double)para[p * 3 + 2];
        double r = g_sums[0]
                 + 0.25 * a * a * g_sums[1]
                 + c * c * g_sums[2]
                 + a * g_sums[3]
                 - 2.0 * c * g_sums[4]
                 + a * c * g_sums[5];
        out[p] = (float)(r * (1.0 / (double)NPTS));
    }
}

__global__ void reset_kernel() {
    if (threadIdx.x < 6) g_sums[threadIdx.x] = 0.0;
    if (threadIdx.x == 0) g_next = 0u;
}

extern "C" void kernel_launch(void* const* d_in, const int* in_sizes, int n_in,
                              void* d_out, int out_size) {
    const float* x     = (const float*)d_in[0];
    const float* para  = (const float*)d_in[1];
    const float* W_in  = (const float*)d_in[2];
    const float* b_in  = (const float*)d_in[3];
    const float* W_hid = (const float*)d_in[4];
    const float* b_hid = (const float*)d_in[5];
    const float* W_out = (const float*)d_in[6];
    const float* b_out = (const float*)d_in[7];
    float* out = (float*)d_out;

    cudaFuncSetAttribute(pinn_kernel, cudaFuncAttributeMaxDynamicSharedMemorySize, SMEM_BYTES);
    pinn_kernel<<<NBLOCKS, THREADS, SMEM_BYTES>>>(
        x, W_in, b_in, W_hid, b_hid, W_out, b_out);
    finalize_kernel<<<(NPARA + 255) / 256, 256>>>(para, out);
    reset_kernel<<<1, 32>>>();
}